// round 8
// baseline (speedup 1.0000x reference)
#include <cuda_runtime.h>
#include <math.h>
#include <stdint.h>

#define BB 16
#define CC 128
#define HW 4096
#define NHEAD 8
#define HDIM 16
#define BH 128
#define OC3 384
#define OUTC 512

// Scratch (allocation-free rule: __device__ globals)
__device__ float g_s[(size_t)BB * CC * HW];        // CPE output
__device__ float g_qkv[(size_t)BB * OC3 * HW];     // qkv per batch [384][4096]
__device__ float g_poslam[(size_t)BB * CC * HW];   // position lambda
__device__ float g_cat[(size_t)BB * 2 * CC * HW];  // [res1 | src*ca] per batch [256][4096]
__device__ float g_pool[BB * CC];
__device__ float g_ca[BB * CC];
__device__ float g_lam[BH * HDIM * HDIM];

__device__ __forceinline__ uint32_t smem_u32(const void* p) {
    uint32_t a;
    asm("{ .reg .u64 tmp; cvta.to.shared.u64 tmp, %1; cvt.u32.u64 %0, tmp; }"
        : "=r"(a) : "l"(p));
    return a;
}
__device__ __forceinline__ void cp_async16(uint32_t dst, const void* src) {
    asm volatile("cp.async.cg.shared.global [%0], [%1], 16;" :: "r"(dst), "l"(src) : "memory");
}
// packed fp32x2 FMA: d = a * b + d (lane-wise)
__device__ __forceinline__ void ffma2(unsigned long long& d, unsigned long long a,
                                      unsigned long long b) {
    asm("fma.rn.f32x2 %0, %1, %2, %0;" : "+l"(d) : "l"(a), "l"(b));
}
__device__ __forceinline__ unsigned long long dup2(float v) {
    unsigned long long r;
    asm("mov.b64 %0, {%1, %1};" : "=l"(r) : "f"(v));
    return r;
}

// ====== double-buffered 128x128x32 GEMM, 256 threads, 8x8 micro-tile, f32x2 FMA ======
// Out[b][o][n] = sum_k W[o][k] * Bmat[b][k][n]
// dynamic smem: As2[2][32][256] (A duplicated pairs) @0, Is[2][32][128] @65536 (96 KB)
#define AS_OFF 0
#define IS_OFF 65536
#define GEMM_SMEM 98304

__global__ void __launch_bounds__(256, 2) k_gemm(const float* __restrict__ Wm,
                                                 const float* __restrict__ Bbase,
                                                 float* __restrict__ Obase,
                                                 int KC, int orpb) {
    extern __shared__ char sm[];
    float* As = (float*)(sm + AS_OFF);       // [2][32][256], value-duplicated pairs
    float* Is = (float*)(sm + IS_OFF);       // [2][32][128]
    uint32_t is_u32 = smem_u32(Is);

    int b = blockIdx.z;
    int o0 = blockIdx.y * 128;
    int n0 = blockIdx.x * 128;
    int tid = threadIdx.x, tx = tid & 15, ty = tid >> 4;
    int am = tid >> 1, ah = (tid & 1) * 16;  // A: 2 threads/row, 16 k each
    int bk = tid >> 3, bn = (tid & 7) * 4;   // B: 8 threads/row, 4x float4 each

    const float* Bb = Bbase + (size_t)b * KC * HW;
    const float* wrowbase = Wm + (size_t)(o0 + am) * KC + ah;

    int nchunk = KC >> 5;

    float4 areg[4];
    // prologue: A(0) regs + B(0) cp.async into buf0
#pragma unroll
    for (int q = 0; q < 4; q++)
        areg[q] = *(const float4*)(wrowbase + q * 4);
#pragma unroll
    for (int u = 0; u < 4; u++)
        cp_async16(is_u32 + (uint32_t)(bk * 512 + (bn + u * 32) * 4),
                   Bb + (size_t)bk * HW + n0 + bn + u * 32);
    asm volatile("cp.async.commit_group;" ::: "memory");
    // store A(0) duplicated into As buf0
    {
        float* a0 = As;
#pragma unroll
        for (int q = 0; q < 4; q++) {
            *(unsigned long long*)(a0 + (ah + q * 4 + 0) * 256 + 2 * am) = dup2(areg[q].x);
            *(unsigned long long*)(a0 + (ah + q * 4 + 1) * 256 + 2 * am) = dup2(areg[q].y);
            *(unsigned long long*)(a0 + (ah + q * 4 + 2) * 256 + 2 * am) = dup2(areg[q].z);
            *(unsigned long long*)(a0 + (ah + q * 4 + 3) * 256 + 2 * am) = dup2(areg[q].w);
        }
    }

    unsigned long long acc2[8][4] = {};   // [row][col-pair], bit pattern 0 == (0.f,0.f)
    int buf = 0;
    for (int ch = 0; ch < nchunk; ch++) {
        int has_next = (ch + 1 < nchunk);
        if (has_next) {
            int k0n = (ch + 1) << 5;
            uint32_t dstb = is_u32 + (uint32_t)((buf ^ 1) * 16384);
            const float* srow = Bb + (size_t)(k0n + bk) * HW + n0;
#pragma unroll
            for (int u = 0; u < 4; u++)
                cp_async16(dstb + (uint32_t)(bk * 512 + (bn + u * 32) * 4),
                           srow + bn + u * 32);
            asm volatile("cp.async.commit_group;" ::: "memory");
#pragma unroll
            for (int q = 0; q < 4; q++)
                areg[q] = *(const float4*)(wrowbase + k0n + q * 4);
            asm volatile("cp.async.wait_group 1;" ::: "memory");
        } else {
            asm volatile("cp.async.wait_group 0;" ::: "memory");
        }
        __syncthreads();
        if (has_next) {
            float* a1 = As + (buf ^ 1) * (32 * 256);
#pragma unroll
            for (int q = 0; q < 4; q++) {
                *(unsigned long long*)(a1 + (ah + q * 4 + 0) * 256 + 2 * am) = dup2(areg[q].x);
                *(unsigned long long*)(a1 + (ah + q * 4 + 1) * 256 + 2 * am) = dup2(areg[q].y);
                *(unsigned long long*)(a1 + (ah + q * 4 + 2) * 256 + 2 * am) = dup2(areg[q].z);
                *(unsigned long long*)(a1 + (ah + q * 4 + 3) * 256 + 2 * am) = dup2(areg[q].w);
            }
        }
        const float* Ab = As + buf * (32 * 256);
        const float* Ib = Is + buf * (32 * 128);
#pragma unroll
        for (int kk = 0; kk < 32; kk++) {
            // duplicated A pairs: (a,a) per value; 2 values per 16B load
            ulonglong2 adA = *(const ulonglong2*)(Ab + kk * 256 + ty * 8);        // m=ty*4+0,1
            ulonglong2 adB = *(const ulonglong2*)(Ab + kk * 256 + ty * 8 + 4);    // m=ty*4+2,3
            ulonglong2 adC = *(const ulonglong2*)(Ab + kk * 256 + ty * 8 + 128);  // m=64+ty*4+0,1
            ulonglong2 adD = *(const ulonglong2*)(Ab + kk * 256 + ty * 8 + 132);  // m=64+ty*4+2,3
            // B column pairs, natively packed
            ulonglong2 bpA = *(const ulonglong2*)(Ib + kk * 128 + tx * 4);        // cols tx*4+0..3
            ulonglong2 bpB = *(const ulonglong2*)(Ib + kk * 128 + tx * 4 + 64);   // cols +64
            unsigned long long ad[8] = {adA.x, adA.y, adB.x, adB.y,
                                        adC.x, adC.y, adD.x, adD.y};
            unsigned long long bp[4] = {bpA.x, bpA.y, bpB.x, bpB.y};
#pragma unroll
            for (int i = 0; i < 8; i++)
#pragma unroll
                for (int j = 0; j < 4; j++)
                    ffma2(acc2[i][j], ad[i], bp[j]);
        }
        __syncthreads();
        buf ^= 1;
    }
    float* Ob = Obase + (size_t)b * orpb * HW;
#pragma unroll
    for (int i = 0; i < 8; i++) {
        int row = o0 + ((i < 4) ? (ty * 4 + i) : (ty * 4 + 64 + i - 4));
        *(ulonglong2*)(Ob + (size_t)row * HW + n0 + tx * 4) =
            make_ulonglong2(acc2[i][0], acc2[i][1]);
        *(ulonglong2*)(Ob + (size_t)row * HW + n0 + tx * 4 + 64) =
            make_ulonglong2(acc2[i][2], acc2[i][3]);
    }
}

// ---------------- CPE: depthwise 3x3 + residual, fused global-mean pool ----------------
__global__ void k_cpe(const float* __restrict__ src, const float* __restrict__ cpe_w) {
    int bc = blockIdx.x;              // b*C + c
    int c = bc & (CC - 1);
    const float* plane = src + (size_t)bc * HW;
    __shared__ float t[66][66];
    __shared__ float red[8];
    for (int i = threadIdx.x; i < 66 * 66; i += blockDim.x) {
        int r = i / 66, q = i % 66;
        int rr = r - 1, qq = q - 1;
        t[r][q] = (rr >= 0 && rr < 64 && qq >= 0 && qq < 64) ? plane[rr * 64 + qq] : 0.f;
    }
    __syncthreads();
    float w[9];
#pragma unroll
    for (int j = 0; j < 9; j++) w[j] = cpe_w[c * 9 + j];
    float psum = 0.f;
    for (int p = threadIdx.x; p < HW; p += blockDim.x) {
        int r = p >> 6, q = p & 63;
        float center = t[r + 1][q + 1];
        psum += center;
        float acc = center;  // residual
#pragma unroll
        for (int dr = 0; dr < 3; dr++)
#pragma unroll
            for (int dc = 0; dc < 3; dc++)
                acc += w[dr * 3 + dc] * t[r + dr][q + dc];
        g_s[(size_t)bc * HW + p] = acc;
    }
#pragma unroll
    for (int off = 16; off; off >>= 1) psum += __shfl_down_sync(0xffffffffu, psum, off);
    if ((threadIdx.x & 31) == 0) red[threadIdx.x >> 5] = psum;
    __syncthreads();
    if (threadIdx.x < 8) {
        psum = red[threadIdx.x];
#pragma unroll
        for (int off = 4; off; off >>= 1) psum += __shfl_down_sync(0xffu, psum, off);
        if (threadIdx.x == 0) g_pool[bc] = psum * (1.f / HW);
    }
}

// ---------------- ECA conv1d + sigmoid ----------------
__global__ void k_ca(const float* __restrict__ w3) {
    int b = blockIdx.x, c = threadIdx.x;
    const float* pp = g_pool + b * CC;
    float x0 = (c > 0) ? pp[c - 1] : 0.f;
    float x1 = pp[c];
    float x2 = (c < CC - 1) ? pp[c + 1] : 0.f;
    float z = w3[0] * x0 + w3[1] * x1 + w3[2] * x2;
    g_ca[b * CC + c] = 1.f / (1.f + expf(-z));
}

// ---------------- scale second half of cat: g_cat[b][128+c][:] = src * ca ----------------
__global__ void k_scale(const float* __restrict__ src) {
    int bc = blockIdx.x;
    int b = bc >> 7, c = bc & 127;
    float ca = g_ca[bc];
    const float* ip = src + (size_t)bc * HW;
    float* op = g_cat + ((size_t)b * 2 * CC + CC + c) * HW;
    for (int p = threadIdx.x * 4; p < HW; p += 256 * 4) {
        float4 v = *(const float4*)(ip + p);
        v.x *= ca; v.y *= ca; v.z *= ca; v.w *= ca;
        *(float4*)(op + p) = v;
    }
}

// ---------- content_lambda via ONLINE softmax: lam[bh][i][o] = sum_n sm(k)[i][n] v[o][n] ----
__global__ void k_lambda() {
    int bh = blockIdx.x;
    int b = bh >> 3, nh = bh & 7;
    const float* kbase = g_qkv + ((size_t)b * OC3 + CC + nh * HDIM) * HW;
    const float* vbase = g_qkv + ((size_t)b * OC3 + 2 * CC + nh * HDIM) * HW;
    __shared__ float ks[HDIM][129];
    __shared__ float vs[HDIM][129];
    int tid = threadIdx.x;
    int i = tid >> 4, o = tid & 15;
    float m = -1e30f, d = 0.f, acc = 0.f;
    for (int c0 = 0; c0 < HW; c0 += 128) {
        for (int t = tid; t < HDIM * 128; t += 256) {
            int r = t >> 7, j = t & 127;
            ks[r][j] = kbase[(size_t)r * HW + c0 + j];
            vs[r][j] = vbase[(size_t)r * HW + c0 + j];
        }
        __syncthreads();
        // chunk max of row i (16 lanes of this row live in this warp)
        float mc = -1e30f;
#pragma unroll
        for (int t = 0; t < 8; t++) mc = fmaxf(mc, ks[i][o + t * 16]);
#pragma unroll
        for (int msk = 1; msk < 16; msk <<= 1)
            mc = fmaxf(mc, __shfl_xor_sync(0xffffffffu, mc, msk));
        float mnew = fmaxf(m, mc);
        float corr = expf(m - mnew);
        d *= corr; acc *= corr;
        // exp in place + chunk denom
        float ps = 0.f;
#pragma unroll
        for (int t = 0; t < 8; t++) {
            float e = expf(ks[i][o + t * 16] - mnew);
            ks[i][o + t * 16] = e;
            ps += e;
        }
#pragma unroll
        for (int msk = 1; msk < 16; msk <<= 1)
            ps += __shfl_xor_sync(0xffffffffu, ps, msk);
        d += ps;
        m = mnew;
        __syncwarp();   // row i's exp writes visible within the owning warp
#pragma unroll 8
        for (int j = 0; j < 128; j++) acc += ks[i][j] * vs[o][j];
        __syncthreads();
    }
    g_lam[(bh * HDIM + i) * HDIM + o] = acc / d;
}

// ---------------- position lambda: depthwise 5x5 of v ----------------
__global__ void k_pos(const float* __restrict__ rel) {
    int bc = blockIdx.x;
    int b = bc >> 7, c = bc & 127;
    const float* vp = g_qkv + ((size_t)b * OC3 + 2 * CC + c) * HW;
    const float* w = rel + (c & 15) * 25;
    __shared__ float t[68][68];
    for (int i = threadIdx.x; i < 68 * 68; i += blockDim.x) {
        int r = i / 68, q = i % 68;
        int rr = r - 2, qq = q - 2;
        t[r][q] = (rr >= 0 && rr < 64 && qq >= 0 && qq < 64) ? vp[rr * 64 + qq] : 0.f;
    }
    __syncthreads();
    float wr[25];
#pragma unroll
    for (int j = 0; j < 25; j++) wr[j] = w[j];
    for (int p = threadIdx.x; p < HW; p += blockDim.x) {
        int r = p >> 6, q = p & 63;
        float acc = 0.f;
#pragma unroll
        for (int dr = 0; dr < 5; dr++)
#pragma unroll
            for (int dc = 0; dc < 5; dc++)
                acc += wr[dr * 5 + dc] * t[r + dr][q + dc];
        g_poslam[(size_t)bc * HW + p] = acc;
    }
}

// ---------------- combine: cat[0:128] = 0.25 * (q^T lam) + q * poslam ----------------
__global__ void k_combine() {
    int bh = blockIdx.y;
    int b = bh >> 3, nh = bh & 7;
    int n = blockIdx.x * 256 + threadIdx.x;
    __shared__ float lam[HDIM][HDIM + 1];
    lam[threadIdx.x >> 4][threadIdx.x & 15] = g_lam[bh * 256 + threadIdx.x];
    __syncthreads();
    const float* qbase = g_qkv + ((size_t)b * OC3 + nh * HDIM) * HW;
    const float* plbase = g_poslam + (size_t)(b * CC + nh * HDIM) * HW;
    float* rbase = g_cat + ((size_t)b * 2 * CC + nh * HDIM) * HW;
    float qv[16];
#pragma unroll
    for (int i = 0; i < 16; i++) qv[i] = qbase[(size_t)i * HW + n];
    const float scaling = 0.25f;  // HD^-0.5
#pragma unroll
    for (int o = 0; o < 16; o++) {
        float cacc = 0.f;
#pragma unroll
        for (int i = 0; i < 16; i++) cacc += qv[i] * lam[i][o];
        rbase[(size_t)o * HW + n] = cacc * scaling + qv[o] * plbase[(size_t)o * HW + n];
    }
}

extern "C" void kernel_launch(void* const* d_in, const int* in_sizes, int n_in,
                              void* d_out, int out_size) {
    const float* src    = (const float*)d_in[0];  // (16,128,64,64)
    const float* cpe_w  = (const float*)d_in[1];  // (128,1,3,3)
    const float* qkv_w  = (const float*)d_in[2];  // (384,128)
    const float* rel    = (const float*)d_in[3];  // (16,5,5)
    const float* c1d    = (const float*)d_in[4];  // (3,)
    const float* out_w  = (const float*)d_in[5];  // (512,256)
    float* out = (float*)d_out;                   // (16,512,64,64)

    static int smem_set = 0;
    if (!smem_set) {
        cudaFuncSetAttribute(k_gemm, cudaFuncAttributeMaxDynamicSharedMemorySize, GEMM_SMEM);
        smem_set = 1;
    }

    float* d_s;    cudaGetSymbolAddress((void**)&d_s, g_s);
    float* d_qkv;  cudaGetSymbolAddress((void**)&d_qkv, g_qkv);
    float* d_cat;  cudaGetSymbolAddress((void**)&d_cat, g_cat);

    k_cpe<<<BB * CC, 256>>>(src, cpe_w);
    k_ca<<<BB, CC>>>(c1d);
    k_scale<<<BB * CC, 256>>>(src);
    // QKV GEMM: M=384, N=4096, K=128
    k_gemm<<<dim3(HW / 128, OC3 / 128, BB), 256, GEMM_SMEM>>>(qkv_w, d_s, d_qkv, CC, OC3);
    k_lambda<<<BH, 256>>>();
    k_pos<<<BB * CC, 256>>>(rel);
    k_combine<<<dim3(HW / 256, BH), 256>>>();
    // Final GEMM: M=512, N=4096, K=256 over g_cat
    k_gemm<<<dim3(HW / 128, OUTC / 128, BB), 256, GEMM_SMEM>>>(out_w, d_cat, out, 2 * CC, OUTC);
}

// round 12
// speedup vs baseline: 1.2927x; 1.2927x over previous
#include <cuda_runtime.h>
#include <math.h>
#include <stdint.h>

#define BB 16
#define CC 128
#define HW 4096
#define NHEAD 8
#define HDIM 16
#define BH 128
#define OC3 384
#define OUTC 512

// Scratch (allocation-free rule: __device__ globals)
__device__ float g_s[(size_t)BB * CC * HW];        // CPE output
__device__ float g_qkv[(size_t)BB * OC3 * HW];     // qkv per batch [384][4096]
__device__ float g_poslam[(size_t)BB * CC * HW];   // position lambda
__device__ float g_cat[(size_t)BB * 2 * CC * HW];  // [res1 | src*ca] per batch [256][4096]
__device__ float g_pool[BB * CC];
__device__ float g_ca[BB * CC];
__device__ float g_lam[BH * HDIM * HDIM];
__device__ float g_wqkvT[CC * OC3];                // W_qkv^T [128][384]
__device__ float g_woutT[2 * CC * OUTC];           // W_out^T [256][512]
__device__ float g_lacc[BH * 8 * 256];             // lambda partials (unnormalized)
__device__ float g_lm[BH * 8 * HDIM];
__device__ float g_ld[BH * 8 * HDIM];

__device__ __forceinline__ uint32_t smem_u32(const void* p) {
    uint32_t a;
    asm("{ .reg .u64 tmp; cvta.to.shared.u64 tmp, %1; cvt.u32.u64 %0, tmp; }"
        : "=r"(a) : "l"(p));
    return a;
}
__device__ __forceinline__ void cp_async16(uint32_t dst, const void* src) {
    asm volatile("cp.async.cg.shared.global [%0], [%1], 16;" :: "r"(dst), "l"(src) : "memory");
}

// ---------------- weight transpose: wt[k][o] = w[o][k] ----------------
__global__ void k_transpose(const float* __restrict__ w, float* __restrict__ wt,
                            int M, int K) {
    int idx = blockIdx.x * 256 + threadIdx.x;
    if (idx < M * K) {
        int o = idx / K, k = idx - o * K;
        wt[k * M + o] = w[idx];
    }
}

// ====== double-buffered 128x128x32 GEMM, 256 threads, 8x8 micro-tile ======
// Out[b][o][n] = sum_k Wt[k][o] * Bmat[b][k][n]   (Wt pre-transposed, row stride Mtot)
// dynamic smem: As[2][32][128] @0, Is[2][32][128] @32768 (64 KB)
#define AS_OFF 0
#define IS_OFF 32768
#define GEMM_SMEM 65536

__global__ void __launch_bounds__(256, 2) k_gemm(const float* __restrict__ Wt,
                                                 const float* __restrict__ Bbase,
                                                 float* __restrict__ Obase,
                                                 int KC, int Mtot) {
    extern __shared__ char sm[];
    float* As = (float*)(sm + AS_OFF);       // [2][32][128]
    float* Is = (float*)(sm + IS_OFF);       // [2][32][128]
    uint32_t as_u32 = smem_u32(As);
    uint32_t is_u32 = smem_u32(Is);

    int b = blockIdx.z;
    int o0 = blockIdx.y * 128;
    int n0 = blockIdx.x * 128;
    int tid = threadIdx.x, tx = tid & 15, ty = tid >> 4;
    int bk = tid >> 3, bn = (tid & 7) * 4;   // loaders: 8 threads/row, 4x float4 each

    const float* Bb = Bbase + (size_t)b * KC * HW;

    int nchunk = KC >> 5;

    // prologue: A(0) + B(0) cp.async into buf0
#pragma unroll
    for (int u = 0; u < 4; u++) {
        cp_async16(as_u32 + (uint32_t)(bk * 512 + (bn + u * 32) * 4),
                   Wt + (size_t)bk * Mtot + o0 + bn + u * 32);
        cp_async16(is_u32 + (uint32_t)(bk * 512 + (bn + u * 32) * 4),
                   Bb + (size_t)bk * HW + n0 + bn + u * 32);
    }
    asm volatile("cp.async.commit_group;" ::: "memory");

    float acc[8][8] = {};
    int buf = 0;
    for (int ch = 0; ch < nchunk; ch++) {
        int has_next = (ch + 1 < nchunk);
        if (has_next) {
            int k0n = (ch + 1) << 5;
            uint32_t boff = (uint32_t)((buf ^ 1) * 16384);
            const float* arow = Wt + (size_t)(k0n + bk) * Mtot + o0;
            const float* srow = Bb + (size_t)(k0n + bk) * HW + n0;
#pragma unroll
            for (int u = 0; u < 4; u++) {
                cp_async16(as_u32 + boff + (uint32_t)(bk * 512 + (bn + u * 32) * 4),
                           arow + bn + u * 32);
                cp_async16(is_u32 + boff + (uint32_t)(bk * 512 + (bn + u * 32) * 4),
                           srow + bn + u * 32);
            }
            asm volatile("cp.async.commit_group;" ::: "memory");
            asm volatile("cp.async.wait_group 1;" ::: "memory");
        } else {
            asm volatile("cp.async.wait_group 0;" ::: "memory");
        }
        __syncthreads();
        const float* Ab = As + buf * (32 * 128);
        const float* Ib = Is + buf * (32 * 128);
#pragma unroll
        for (int kk = 0; kk < 32; kk++) {
            float4 a0 = *(const float4*)(Ab + kk * 128 + ty * 4);
            float4 a1 = *(const float4*)(Ab + kk * 128 + ty * 4 + 64);
            float4 b0 = *(const float4*)(Ib + kk * 128 + tx * 4);
            float4 b1 = *(const float4*)(Ib + kk * 128 + tx * 4 + 64);
            float ar[8] = {a0.x, a0.y, a0.z, a0.w, a1.x, a1.y, a1.z, a1.w};
            float br[8] = {b0.x, b0.y, b0.z, b0.w, b1.x, b1.y, b1.z, b1.w};
#pragma unroll
            for (int i = 0; i < 8; i++)
#pragma unroll
                for (int j = 0; j < 8; j++)
                    acc[i][j] += ar[i] * br[j];
        }
        __syncthreads();
        buf ^= 1;
    }
    float* Ob = Obase + (size_t)b * Mtot * HW;
#pragma unroll
    for (int i = 0; i < 8; i++) {
        int row = o0 + ((i < 4) ? (ty * 4 + i) : (ty * 4 + 64 + i - 4));
        float4 v0 = make_float4(acc[i][0], acc[i][1], acc[i][2], acc[i][3]);
        float4 v1 = make_float4(acc[i][4], acc[i][5], acc[i][6], acc[i][7]);
        *(float4*)(Ob + (size_t)row * HW + n0 + tx * 4) = v0;
        *(float4*)(Ob + (size_t)row * HW + n0 + tx * 4 + 64) = v1;
    }
}

// ---------------- CPE: depthwise 3x3 + residual, fused global-mean pool ----------------
__global__ void k_cpe(const float* __restrict__ src, const float* __restrict__ cpe_w) {
    int bc = blockIdx.x;              // b*C + c
    int c = bc & (CC - 1);
    const float* plane = src + (size_t)bc * HW;
    __shared__ float t[66][66];
    __shared__ float red[8];
    for (int i = threadIdx.x; i < 66 * 66; i += blockDim.x) {
        int r = i / 66, q = i % 66;
        int rr = r - 1, qq = q - 1;
        t[r][q] = (rr >= 0 && rr < 64 && qq >= 0 && qq < 64) ? plane[rr * 64 + qq] : 0.f;
    }
    __syncthreads();
    float w[9];
#pragma unroll
    for (int j = 0; j < 9; j++) w[j] = cpe_w[c * 9 + j];
    float psum = 0.f;
    for (int p = threadIdx.x; p < HW; p += blockDim.x) {
        int r = p >> 6, q = p & 63;
        float center = t[r + 1][q + 1];
        psum += center;
        float acc = center;  // residual
#pragma unroll
        for (int dr = 0; dr < 3; dr++)
#pragma unroll
            for (int dc = 0; dc < 3; dc++)
                acc += w[dr * 3 + dc] * t[r + dr][q + dc];
        g_s[(size_t)bc * HW + p] = acc;
    }
#pragma unroll
    for (int off = 16; off; off >>= 1) psum += __shfl_down_sync(0xffffffffu, psum, off);
    if ((threadIdx.x & 31) == 0) red[threadIdx.x >> 5] = psum;
    __syncthreads();
    if (threadIdx.x < 8) {
        psum = red[threadIdx.x];
#pragma unroll
        for (int off = 4; off; off >>= 1) psum += __shfl_down_sync(0xffu, psum, off);
        if (threadIdx.x == 0) g_pool[bc] = psum * (1.f / HW);
    }
}

// ---------------- ECA conv1d + sigmoid ----------------
__global__ void k_ca(const float* __restrict__ w3) {
    int b = blockIdx.x, c = threadIdx.x;
    const float* pp = g_pool + b * CC;
    float x0 = (c > 0) ? pp[c - 1] : 0.f;
    float x1 = pp[c];
    float x2 = (c < CC - 1) ? pp[c + 1] : 0.f;
    float z = w3[0] * x0 + w3[1] * x1 + w3[2] * x2;
    g_ca[b * CC + c] = 1.f / (1.f + expf(-z));
}

// ---------------- scale second half of cat: g_cat[b][128+c][:] = src * ca ----------------
__global__ void k_scale(const float* __restrict__ src) {
    int bc = blockIdx.x;
    int b = bc >> 7, c = bc & 127;
    float ca = g_ca[bc];
    const float* ip = src + (size_t)bc * HW;
    float* op = g_cat + ((size_t)b * 2 * CC + CC + c) * HW;
    for (int p = threadIdx.x * 4; p < HW; p += 256 * 4) {
        float4 v = *(const float4*)(ip + p);
        v.x *= ca; v.y *= ca; v.z *= ca; v.w *= ca;
        *(float4*)(op + p) = v;
    }
}

// ---------- content_lambda phase 1: per-512-col partial online softmax ----------
// block = bh*8 + chunk; outputs unnormalized acc (rel. to local max m), plus (m, d)
__global__ void k_lambda_part() {
    int blk = blockIdx.x;
    int bh = blk >> 3, chunk = blk & 7;
    int b = bh >> 3, nh = bh & 7;
    const float* kbase = g_qkv + ((size_t)b * OC3 + CC + nh * HDIM) * HW + chunk * 512;
    const float* vbase = g_qkv + ((size_t)b * OC3 + 2 * CC + nh * HDIM) * HW + chunk * 512;
    __shared__ float ks[HDIM][129];
    __shared__ float vs[HDIM][129];
    int tid = threadIdx.x;
    int i = tid >> 4, o = tid & 15;
    float m = -1e30f, d = 0.f, acc = 0.f;
    for (int c0 = 0; c0 < 512; c0 += 128) {
        for (int t = tid; t < HDIM * 128; t += 256) {
            int r = t >> 7, j = t & 127;
            ks[r][j] = kbase[(size_t)r * HW + c0 + j];
            vs[r][j] = vbase[(size_t)r * HW + c0 + j];
        }
        __syncthreads();
        float mc = -1e30f;
#pragma unroll
        for (int t = 0; t < 8; t++) mc = fmaxf(mc, ks[i][o + t * 16]);
#pragma unroll
        for (int msk = 1; msk < 16; msk <<= 1)
            mc = fmaxf(mc, __shfl_xor_sync(0xffffffffu, mc, msk));
        float mnew = fmaxf(m, mc);
        float corr = expf(m - mnew);
        d *= corr; acc *= corr;
        float ps = 0.f;
#pragma unroll
        for (int t = 0; t < 8; t++) {
            float e = expf(ks[i][o + t * 16] - mnew);
            ks[i][o + t * 16] = e;
            ps += e;
        }
#pragma unroll
        for (int msk = 1; msk < 16; msk <<= 1)
            ps += __shfl_xor_sync(0xffffffffu, ps, msk);
        d += ps;
        m = mnew;
        __syncwarp();
#pragma unroll 8
        for (int j = 0; j < 128; j++) acc += ks[i][j] * vs[o][j];
        __syncthreads();
    }
    g_lacc[blk * 256 + tid] = acc;
    if (o == 0) {
        g_lm[blk * HDIM + i] = m;
        g_ld[blk * HDIM + i] = d;
    }
}

// ---------- content_lambda phase 2: merge 8 partials ----------
__global__ void k_lambda_merge() {
    int bh = blockIdx.x;
    int tid = threadIdx.x;
    int i = tid >> 4;
    float M = -1e30f;
#pragma unroll
    for (int c = 0; c < 8; c++) M = fmaxf(M, g_lm[(bh * 8 + c) * HDIM + i]);
    float acc = 0.f, d = 0.f;
#pragma unroll
    for (int c = 0; c < 8; c++) {
        float w = expf(g_lm[(bh * 8 + c) * HDIM + i] - M);
        acc += g_lacc[(bh * 8 + c) * 256 + tid] * w;
        d += g_ld[(bh * 8 + c) * HDIM + i] * w;
    }
    g_lam[bh * 256 + tid] = acc / d;
}

// ---------------- position lambda: depthwise 5x5 of v ----------------
__global__ void k_pos(const float* __restrict__ rel) {
    int bc = blockIdx.x;
    int b = bc >> 7, c = bc & 127;
    const float* vp = g_qkv + ((size_t)b * OC3 + 2 * CC + c) * HW;
    const float* w = rel + (c & 15) * 25;
    __shared__ float t[68][68];
    for (int i = threadIdx.x; i < 68 * 68; i += blockDim.x) {
        int r = i / 68, q = i % 68;
        int rr = r - 2, qq = q - 2;
        t[r][q] = (rr >= 0 && rr < 64 && qq >= 0 && qq < 64) ? vp[rr * 64 + qq] : 0.f;
    }
    __syncthreads();
    float wr[25];
#pragma unroll
    for (int j = 0; j < 25; j++) wr[j] = w[j];
    for (int p = threadIdx.x; p < HW; p += blockDim.x) {
        int r = p >> 6, q = p & 63;
        float acc = 0.f;
#pragma unroll
        for (int dr = 0; dr < 5; dr++)
#pragma unroll
            for (int dc = 0; dc < 5; dc++)
                acc += wr[dr * 5 + dc] * t[r + dr][q + dc];
        g_poslam[(size_t)bc * HW + p] = acc;
    }
}

// ---------------- combine: cat[0:128] = 0.25 * (q^T lam) + q * poslam ----------------
__global__ void k_combine() {
    int bh = blockIdx.y;
    int b = bh >> 3, nh = bh & 7;
    int n = blockIdx.x * 256 + threadIdx.x;
    __shared__ float lam[HDIM][HDIM + 1];
    lam[threadIdx.x >> 4][threadIdx.x & 15] = g_lam[bh * 256 + threadIdx.x];
    __syncthreads();
    const float* qbase = g_qkv + ((size_t)b * OC3 + nh * HDIM) * HW;
    const float* plbase = g_poslam + (size_t)(b * CC + nh * HDIM) * HW;
    float* rbase = g_cat + ((size_t)b * 2 * CC + nh * HDIM) * HW;
    float qv[16];
#pragma unroll
    for (int i = 0; i < 16; i++) qv[i] = qbase[(size_t)i * HW + n];
    const float scaling = 0.25f;  // HD^-0.5
#pragma unroll
    for (int o = 0; o < 16; o++) {
        float cacc = 0.f;
#pragma unroll
        for (int i = 0; i < 16; i++) cacc += qv[i] * lam[i][o];
        rbase[(size_t)o * HW + n] = cacc * scaling + qv[o] * plbase[(size_t)o * HW + n];
    }
}

extern "C" void kernel_launch(void* const* d_in, const int* in_sizes, int n_in,
                              void* d_out, int out_size) {
    const float* src    = (const float*)d_in[0];  // (16,128,64,64)
    const float* cpe_w  = (const float*)d_in[1];  // (128,1,3,3)
    const float* qkv_w  = (const float*)d_in[2];  // (384,128)
    const float* rel    = (const float*)d_in[3];  // (16,5,5)
    const float* c1d    = (const float*)d_in[4];  // (3,)
    const float* out_w  = (const float*)d_in[5];  // (512,256)
    float* out = (float*)d_out;                   // (16,512,64,64)

    cudaFuncSetAttribute(k_gemm, cudaFuncAttributeMaxDynamicSharedMemorySize, GEMM_SMEM);

    float* d_s;      cudaGetSymbolAddress((void**)&d_s, g_s);
    float* d_qkv;    cudaGetSymbolAddress((void**)&d_qkv, g_qkv);
    float* d_cat;    cudaGetSymbolAddress((void**)&d_cat, g_cat);
    float* d_wqkvT;  cudaGetSymbolAddress((void**)&d_wqkvT, g_wqkvT);
    float* d_woutT;  cudaGetSymbolAddress((void**)&d_woutT, g_woutT);

    k_transpose<<<(OC3 * CC + 255) / 256, 256>>>(qkv_w, d_wqkvT, OC3, CC);
    k_transpose<<<(OUTC * 2 * CC + 255) / 256, 256>>>(out_w, d_woutT, OUTC, 2 * CC);
    k_cpe<<<BB * CC, 256>>>(src, cpe_w);
    k_ca<<<BB, CC>>>(c1d);
    k_scale<<<BB * CC, 256>>>(src);
    // QKV GEMM: M=384, N=4096, K=128
    k_gemm<<<dim3(HW / 128, OC3 / 128, BB), 256, GEMM_SMEM>>>(d_wqkvT, d_s, d_qkv, CC, OC3);
    k_lambda_part<<<BH * 8, 256>>>();
    k_lambda_merge<<<BH, 256>>>();
    k_pos<<<BB * CC, 256>>>(rel);
    k_combine<<<dim3(HW / 256, BH), 256>>>();
    // Final GEMM: M=512, N=4096, K=256 over g_cat
    k_gemm<<<dim3(HW / 128, OUTC / 128, BB), 256, GEMM_SMEM>>>(d_woutT, d_cat, out, 2 * CC, OUTC);
}